// round 10
// baseline (speedup 1.0000x reference)
#include <cuda_runtime.h>
#include <cuda_fp16.h>

#define NLAT_IN  181
#define NLON_IN  360
#define NLAT_OUT 361
#define NLON_OUT 720
#define KSIZE    3
#define CIN      16
#define COUT     16
#define NNZ      8192
#define NBIN     (NLAT_OUT * 2)   // (hi, parity)
#define MAXB     128
#define NWS      16               // sort warps
#define EPW      (NNZ / NWS)      // 512 elements per sort warp
#define NEIN     (NLAT_IN * KSIZE)       // 543 einsum blocks
#define SORT_SMEM ((NWS * NBIN + 768) * 4)
#define NROW     (KSIZE * NLAT_IN)       // 543 xw rows

// xw: [row][h][w] as uint4 (8 fp16 channels packed). 543*2*360*16B = 6.25MB
__device__ uint4 d_xw4[NROW * 2 * NLON_IN];
__device__ int2  d_ent[NNZ];           // {meta, val-bits}; meta=(row*720)<<9 | s
__device__ int   d_pack[NNZ];          // bin<<16 | warp-local stable rank
__device__ int   d_offsets[NBIN + 1];

// ---------------------------------------------------------------------------
// Fused: blocks 0..542 do the channel-mix einsum; block 543 does the full
// stable counting sort (16 worker warps, 768 threads for the 722-bin scan).
__global__ void __launch_bounds__(768)
k_prep(const float* __restrict__ x, const float* __restrict__ wgt,
       const int* __restrict__ ker_idx, const int* __restrict__ row_idx,
       const int* __restrict__ col_idx, const float* __restrict__ vals) {
    int t = threadIdx.x;

    if (blockIdx.x == NEIN) {
        // ---------------- sort path ----------------
        extern __shared__ int swh[];      // [NWS][NBIN] counts, then [768] scan
        int* s = swh + NWS * NBIN;
        int w = t >> 5, lane = t & 31;

        for (int i = t; i < NWS * NBIN; i += 768) swh[i] = 0;
        __syncthreads();

        // Phase 1: per-warp stable ranks; spill (bin, rank) to d_pack
        if (w < NWS) {
            for (int r = 0; r < EPW / 32; r++) {
                int i   = w * EPW + r * 32 + lane;
                int col = col_idx[i];
                int hi  = col / NLON_OUT;
                int p   = col - hi * NLON_OUT;
                int bin = hi * 2 + (p & 1);
                unsigned match = __match_any_sync(0xffffffffu, bin);
                int rl   = __popc(match & ((1u << lane) - 1u));
                int base = swh[w * NBIN + bin];
                d_pack[i] = (bin << 16) | (base + rl);
                __syncwarp();
                if (rl == 0) swh[w * NBIN + bin] = base + __popc(match);
                __syncwarp();
            }
        }
        __syncthreads();

        // Phase 2: per-bin warp prefix + cross-bin exclusive scan
        int total = 0;
        if (t < NBIN) {
            int run = 0;
#pragma unroll
            for (int ww = 0; ww < NWS; ww++) {
                int v = swh[ww * NBIN + t];
                swh[ww * NBIN + t] = run;
                run += v;
            }
            total = run;
        }
        s[t] = total;
        __syncthreads();
        for (int d = 1; d < 768; d <<= 1) {
            int v = (t >= d) ? s[t - d] : 0;
            __syncthreads();
            s[t] += v;
            __syncthreads();
        }
        if (t < NBIN) {
            int excl = s[t] - total;
            d_offsets[t] = excl;
            if (t == NBIN - 1) d_offsets[NBIN] = excl + total;
#pragma unroll
            for (int ww = 0; ww < NWS; ww++) swh[ww * NBIN + t] += excl;
        }
        __syncthreads();

        // Phase 3: scatter; meta carries precomputed uint4 row offset
        if (w < NWS) {
            for (int r = 0; r < EPW / 32; r++) {
                int i    = w * EPW + r * 32 + lane;
                int pk   = d_pack[i];
                int bin  = pk >> 16;
                int rank = pk & 0xffff;
                int col  = col_idx[i];
                int hi   = col / NLON_OUT;
                int p    = col - hi * NLON_OUT;
                int pos  = swh[w * NBIN + bin] + rank;
                int row4 = (ker_idx[i] * NLAT_IN + row_idx[i]) * (2 * NLON_IN);
                d_ent[pos] = make_int2((row4 << 9) | (p >> 1),
                                       __float_as_int(vals[i]));
            }
        }
        return;
    }

    // ---------------- einsum path ----------------
    // block b: tin = b % 181, k = b / 181. h=0: ch 0..7, h=1: ch 8..15.
    __shared__ float sw[COUT * CIN];  // [o][c] for this k
    int b   = blockIdx.x;
    int tin = b % NLAT_IN;
    int k   = b / NLAT_IN;
    if (t < COUT * CIN) sw[t] = wgt[t * KSIZE + k];  // wgt[o][c][k]
    __syncthreads();

    int h = (t >= 384) ? 1 : 0;
    int w = t - h * 384;
    if (w >= NLON_IN) return;

    float acc[8];
#pragma unroll
    for (int o = 0; o < 8; o++) acc[o] = 0.f;

#pragma unroll
    for (int c = 0; c < CIN; c++) {
        float xc = x[(c * NLAT_IN + tin) * NLON_IN + w];
#pragma unroll
        for (int o = 0; o < 8; o++)
            acc[o] += xc * sw[(h * 8 + o) * CIN + c];
    }
    __half2 p0 = __floats2half2_rn(acc[0], acc[1]);
    __half2 p1 = __floats2half2_rn(acc[2], acc[3]);
    __half2 p2 = __floats2half2_rn(acc[4], acc[5]);
    __half2 p3 = __floats2half2_rn(acc[6], acc[7]);
    uint4 val;
    val.x = *(unsigned*)&p0;
    val.y = *(unsigned*)&p1;
    val.z = *(unsigned*)&p2;
    val.w = *(unsigned*)&p3;
    d_xw4[(k * NLAT_IN + tin) * (2 * NLON_IN) + h * NLON_IN + w] = val;
}

// ---------------------------------------------------------------------------
// main gather: one block per bin; thread jj owns lon q+2*jj for ALL 16
// channels (two adjacent uint4 loads per entry). Unrolled x2: 4 LDG.128
// in flight per thread.
__global__ void __launch_bounds__(384)
k_main(const float* __restrict__ bias, float* __restrict__ out) {
    __shared__ int2 se[MAXB];
    int b  = blockIdx.x;       // bin
    int hi = b >> 1;
    int q  = b & 1;
    int tid = threadIdx.x;
    int beg = d_offsets[b];
    int cnt = d_offsets[b + 1] - beg;
    if (cnt > MAXB) cnt = MAXB;
    if (tid < cnt) se[tid] = d_ent[beg + tid];
    __syncthreads();

    int jj = tid;
    if (jj >= NLON_IN) return;

    float acc[16];
#pragma unroll
    for (int o = 0; o < 16; o++) acc[o] = 0.f;

    int e = 0;
    for (; e + 1 < cnt; e += 2) {
        int2 ev0 = se[e], ev1 = se[e + 1];
        float v0 = __int_as_float(ev0.y), v1 = __int_as_float(ev1.y);
        int s0 = ev0.x & 511, s1 = ev1.x & 511;
        int w0 = jj - s0; if (w0 < 0) w0 += NLON_IN;
        int w1 = jj - s1; if (w1 < 0) w1 += NLON_IN;
        const uint4* p0 = d_xw4 + (ev0.x >> 9) + w0;
        const uint4* p1 = d_xw4 + (ev1.x >> 9) + w1;
        uint4 a0 = p0[0], b0 = p0[NLON_IN];
        uint4 a1 = p1[0], b1 = p1[NLON_IN];
#pragma unroll
        for (int j = 0; j < 4; j++) {
            float2 fa0 = __half22float2(*(const __half2*)(&a0.x + j));
            float2 fb0 = __half22float2(*(const __half2*)(&b0.x + j));
            float2 fa1 = __half22float2(*(const __half2*)(&a1.x + j));
            float2 fb1 = __half22float2(*(const __half2*)(&b1.x + j));
            acc[2 * j]     += v0 * fa0.x + v1 * fa1.x;
            acc[2 * j + 1] += v0 * fa0.y + v1 * fa1.y;
            acc[8 + 2 * j]     += v0 * fb0.x + v1 * fb1.x;
            acc[8 + 2 * j + 1] += v0 * fb0.y + v1 * fb1.y;
        }
    }
    if (e < cnt) {
        int2 ev = se[e];
        float v = __int_as_float(ev.y);
        int s = ev.x & 511;
        int w = jj - s; if (w < 0) w += NLON_IN;
        const uint4* p = d_xw4 + (ev.x >> 9) + w;
        uint4 a = p[0], bq = p[NLON_IN];
#pragma unroll
        for (int j = 0; j < 4; j++) {
            float2 fa = __half22float2(*(const __half2*)(&a.x + j));
            float2 fb = __half22float2(*(const __half2*)(&bq.x + j));
            acc[2 * j]         += v * fa.x;
            acc[2 * j + 1]     += v * fa.y;
            acc[8 + 2 * j]     += v * fb.x;
            acc[8 + 2 * j + 1] += v * fb.y;
        }
    }

    int lon = q + 2 * jj;
    const int cs = NLAT_OUT * NLON_OUT;
    float* dst = out + hi * NLON_OUT + lon;
#pragma unroll
    for (int o = 0; o < 16; o++) dst[o * cs] = acc[o] + bias[o];
}

// ---------------------------------------------------------------------------
extern "C" void kernel_launch(void* const* d_in, const int* in_sizes, int n_in,
                              void* d_out, int out_size) {
    const float* x       = (const float*)d_in[0];
    const float* weight  = (const float*)d_in[1];
    const float* bias    = (const float*)d_in[2];
    const int*   ker_idx = (const int*)d_in[3];
    const int*   row_idx = (const int*)d_in[4];
    const int*   col_idx = (const int*)d_in[5];
    const float* vals    = (const float*)d_in[6];
    float* out = (float*)d_out;

    (void)in_sizes; (void)n_in; (void)out_size;

    cudaFuncSetAttribute(k_prep, cudaFuncAttributeMaxDynamicSharedMemorySize,
                         SORT_SMEM);
    k_prep<<<NEIN + 1, 768, SORT_SMEM>>>(x, weight, ker_idx, row_idx,
                                         col_idx, vals);
    k_main<<<NBIN, 384>>>(bias, out);
}

// round 11
// speedup vs baseline: 1.5734x; 1.5734x over previous
#include <cuda_runtime.h>
#include <cuda_fp16.h>

#define NLAT_IN  181
#define NLON_IN  360
#define NLAT_OUT 361
#define NLON_OUT 720
#define KSIZE    3
#define CIN      16
#define COUT     16
#define NNZ      8192
#define NBIN     (NLAT_OUT * 2)   // (hi, parity)
#define MAXB     128
#define NEIN     (NLAT_IN * KSIZE)  // 543 einsum blocks
#define NBINB    64                 // binning blocks (128 entries each)
#define NROW     (KSIZE * NLAT_IN)  // 543 xw rows

// xw: [row][h][w] as uint4 (8 fp16 channels packed). 543*2*360*16B = 6.25MB
__device__ uint4 d_xw4[NROW * 2 * NLON_IN];
// Two independent bucket copies (one per channel-half k_main block).
// Entry: {meta, val_bits, orig_idx, unused}; meta = (row4<<9)|s
__device__ int4 d_bk0[NBIN * MAXB];
__device__ int4 d_bk1[NBIN * MAXB];
__device__ int  d_cnt0[NBIN];   // statically zero; each k_main block resets its own
__device__ int  d_cnt1[NBIN];

// ---------------------------------------------------------------------------
// Fused: blocks 0..542 = channel-mix einsum; blocks 543..606 = atomic binning.
__global__ void __launch_bounds__(768)
k_prep(const float* __restrict__ x, const float* __restrict__ wgt,
       const int* __restrict__ ker_idx, const int* __restrict__ row_idx,
       const int* __restrict__ col_idx, const float* __restrict__ vals) {
    int t = threadIdx.x;

    if (blockIdx.x >= NEIN) {
        // ---------------- binning path ----------------
        if (t >= 128) return;
        int i   = (blockIdx.x - NEIN) * 128 + t;
        int col = col_idx[i];
        int hi  = col / NLON_OUT;
        int p   = col - hi * NLON_OUT;
        int bin = hi * 2 + (p & 1);
        int row4 = (ker_idx[i] * NLAT_IN + row_idx[i]) * (2 * NLON_IN);
        int4 ent = make_int4((row4 << 9) | (p >> 1),
                             __float_as_int(vals[i]), i, 0);
        int s0 = atomicAdd(&d_cnt0[bin], 1);
        if (s0 < MAXB) d_bk0[bin * MAXB + s0] = ent;
        int s1 = atomicAdd(&d_cnt1[bin], 1);
        if (s1 < MAXB) d_bk1[bin * MAXB + s1] = ent;
        return;
    }

    // ---------------- einsum path ----------------
    // block b: tin = b % 181, k = b / 181. h=0: ch 0..7, h=1: ch 8..15.
    __shared__ float sw[COUT * CIN];  // [o][c] for this k
    int b   = blockIdx.x;
    int tin = b % NLAT_IN;
    int k   = b / NLAT_IN;
    if (t < COUT * CIN) sw[t] = wgt[t * KSIZE + k];  // wgt[o][c][k]
    __syncthreads();

    int h = (t >= 384) ? 1 : 0;
    int w = t - h * 384;
    if (w >= NLON_IN) return;

    float acc[8];
#pragma unroll
    for (int o = 0; o < 8; o++) acc[o] = 0.f;

#pragma unroll
    for (int c = 0; c < CIN; c++) {
        float xc = x[(c * NLAT_IN + tin) * NLON_IN + w];
#pragma unroll
        for (int o = 0; o < 8; o++)
            acc[o] += xc * sw[(h * 8 + o) * CIN + c];
    }
    __half2 p0 = __floats2half2_rn(acc[0], acc[1]);
    __half2 p1 = __floats2half2_rn(acc[2], acc[3]);
    __half2 p2 = __floats2half2_rn(acc[4], acc[5]);
    __half2 p3 = __floats2half2_rn(acc[6], acc[7]);
    uint4 val;
    val.x = *(unsigned*)&p0;
    val.y = *(unsigned*)&p1;
    val.z = *(unsigned*)&p2;
    val.w = *(unsigned*)&p3;
    d_xw4[(k * NLAT_IN + tin) * (2 * NLON_IN) + h * NLON_IN + w] = val;
}

// ---------------------------------------------------------------------------
// main gather: one block per (bin, channel-half). Loads its PRIVATE bucket
// copy, sorts it by original index in smem (restores determinism), resets
// its own counter, then accumulates: 1 x LDG.128 per entry, unrolled x4.
__global__ void __launch_bounds__(384)
k_main(const float* __restrict__ bias, float* __restrict__ out) {
    __shared__ int  sidx[MAXB];
    __shared__ int2 sraw[MAXB];
    __shared__ int2 se[MAXB];     // sorted {meta, val}
    int bb = blockIdx.x;
    int b  = bb >> 1;          // bin
    int h  = bb & 1;           // channel half
    int hi = b >> 1;
    int q  = b & 1;
    int tid = threadIdx.x;

    int* cntp = h ? d_cnt1 : d_cnt0;
    const int4* bk = (h ? d_bk1 : d_bk0) + b * MAXB;

    int cnt = cntp[b];
    if (cnt > MAXB) cnt = MAXB;
    if (tid < cnt) {
        int4 e = bk[tid];
        sraw[tid] = make_int2(e.x, e.y);
        sidx[tid] = e.z;
    }
    __syncthreads();
    if (tid == 0) cntp[b] = 0;          // reset for next graph replay
    // deterministic order: rank by original index (unique)
    if (tid < cnt) {
        int my = sidx[tid];
        int r = 0;
        for (int j = 0; j < cnt; j++) r += (sidx[j] < my);
        se[r] = sraw[tid];
    }
    __syncthreads();

    int jj = tid;
    if (jj >= NLON_IN) return;

    const uint4* __restrict__ xbase = d_xw4 + h * NLON_IN;
    float acc[8];
#pragma unroll
    for (int o = 0; o < 8; o++) acc[o] = 0.f;

    int e = 0;
    for (; e + 3 < cnt; e += 4) {
        uint4 dd[4];
        float vv[4];
#pragma unroll
        for (int u = 0; u < 4; u++) {
            int2 ev = se[e + u];
            vv[u] = __int_as_float(ev.y);
            int s = ev.x & 511;
            int w = jj - s; if (w < 0) w += NLON_IN;
            dd[u] = xbase[(ev.x >> 9) + w];
        }
#pragma unroll
        for (int u = 0; u < 4; u++) {
            float v = vv[u];
            float2 f0 = __half22float2(*(const __half2*)&dd[u].x);
            float2 f1 = __half22float2(*(const __half2*)&dd[u].y);
            float2 f2 = __half22float2(*(const __half2*)&dd[u].z);
            float2 f3 = __half22float2(*(const __half2*)&dd[u].w);
            acc[0] += v * f0.x; acc[1] += v * f0.y;
            acc[2] += v * f1.x; acc[3] += v * f1.y;
            acc[4] += v * f2.x; acc[5] += v * f2.y;
            acc[6] += v * f3.x; acc[7] += v * f3.y;
        }
    }
    for (; e < cnt; e++) {
        int2 ev = se[e];
        float v = __int_as_float(ev.y);
        int s = ev.x & 511;
        int w = jj - s; if (w < 0) w += NLON_IN;
        uint4 dd = xbase[(ev.x >> 9) + w];
        float2 f0 = __half22float2(*(const __half2*)&dd.x);
        float2 f1 = __half22float2(*(const __half2*)&dd.y);
        float2 f2 = __half22float2(*(const __half2*)&dd.z);
        float2 f3 = __half22float2(*(const __half2*)&dd.w);
        acc[0] += v * f0.x; acc[1] += v * f0.y;
        acc[2] += v * f1.x; acc[3] += v * f1.y;
        acc[4] += v * f2.x; acc[5] += v * f2.y;
        acc[6] += v * f3.x; acc[7] += v * f3.y;
    }

    int lon = q + 2 * jj;
    const int cs = NLAT_OUT * NLON_OUT;
    float* dst = out + (h * 8) * cs + hi * NLON_OUT + lon;
#pragma unroll
    for (int o = 0; o < 8; o++) dst[o * cs] = acc[o] + bias[h * 8 + o];
}

// ---------------------------------------------------------------------------
extern "C" void kernel_launch(void* const* d_in, const int* in_sizes, int n_in,
                              void* d_out, int out_size) {
    const float* x       = (const float*)d_in[0];
    const float* weight  = (const float*)d_in[1];
    const float* bias    = (const float*)d_in[2];
    const int*   ker_idx = (const int*)d_in[3];
    const int*   row_idx = (const int*)d_in[4];
    const int*   col_idx = (const int*)d_in[5];
    const float* vals    = (const float*)d_in[6];
    float* out = (float*)d_out;

    (void)in_sizes; (void)n_in; (void)out_size;

    k_prep<<<NEIN + NBINB, 768>>>(x, weight, ker_idx, row_idx, col_idx, vals);
    k_main<<<NBIN * 2, 384>>>(bias, out);
}